// round 16
// baseline (speedup 1.0000x reference)
#include <cuda_runtime.h>
#include <cuda_fp16.h>
#include <math.h>
#include <stdint.h>

// Problem constants
#define BB 128      // batch
#define TT 256      // seq len
#define DD 256      // input dim
#define HH 1024     // hidden dim
#define CC 10       // classes
#define N4 4096     // 4*HH
#define NCTA 128    // persistent CTAs (one per SM)

// Step kernel constants
#define STEP_THR 512                    // 16 warps: 2 k-groups x (4m x 2n)
#define WROW 2064                       // 1024 fp16 = 2048B + 16B pad
#define S_WT 0                          // W tile: 64 x WROW = 132096
#define S_ABUF (64 * WROW)              // 132096
#define ACH_SZ 16384                    // one A chunk: 64 rows x 128 fp16 (2 subtiles)
#define NBUF 6                          // kg0: bufs 0..2, kg1: bufs 3..5
#define STEP_SMEM (S_ABUF + NBUF * ACH_SZ)  // 230400 (<= 227KB opt-in)
#define S_RED (S_ABUF + ACH_SZ)         // reduction staging (16KB, drained buf1)

// xg MMA kernel constants (proven)
#define XG_SMEM 65536
#define XCROWH 136

// ---------------------------------------------------------------------------
// Device globals
// ---------------------------------------------------------------------------
__device__ __half g_xg[(size_t)TT * BB * N4];     // [t*128+b][n=u*4+j] fp16
__device__ __half g_xA[(size_t)TT * BB * DD];     // x rows r=t*128+b fp16
__device__ __half g_Wxp[(size_t)N4 * DD];         // Wx^T packed fp16
__device__ float  g_bbp[N4];                      // bias packed fp32
__device__ __half g_Wp[(size_t)N4 * HH];          // Wh^T packed fp16
__device__ __half g_h[2][BB * HH];                // h state fp16
__device__ unsigned g_barc[2];                    // per-mg-group grid barriers

// ---------------------------------------------------------------------------
// PTX helpers
// ---------------------------------------------------------------------------
__device__ __forceinline__ uint32_t smem_u32(const void* p) {
    uint32_t a;
    asm("{ .reg .u64 t; cvta.to.shared.u64 t, %1; cvt.u32.u64 %0, t; }" : "=r"(a) : "l"(p));
    return a;
}
__device__ __forceinline__ void cp_async16(uint32_t dst, const void* src) {
    asm volatile("cp.async.cg.shared.global [%0], [%1], 16;" :: "r"(dst), "l"(src));
}
#define CP_COMMIT() asm volatile("cp.async.commit_group;" ::: "memory")
#define CP_WAIT(n)  asm volatile("cp.async.wait_group %0;" :: "n"(n) : "memory")

__device__ __forceinline__ void ldmx4(uint32_t* r, uint32_t addr) {
    asm volatile("ldmatrix.sync.aligned.m8n8.x4.shared.b16 {%0,%1,%2,%3}, [%4];"
                 : "=r"(r[0]), "=r"(r[1]), "=r"(r[2]), "=r"(r[3]) : "r"(addr));
}
__device__ __forceinline__ void mma16816(float* d, const uint32_t* a, uint32_t b0, uint32_t b1) {
    asm volatile("mma.sync.aligned.m16n8k16.row.col.f32.f16.f16.f32 "
                 "{%0,%1,%2,%3}, {%4,%5,%6,%7}, {%8,%9}, {%0,%1,%2,%3};"
                 : "+f"(d[0]), "+f"(d[1]), "+f"(d[2]), "+f"(d[3])
                 : "r"(a[0]), "r"(a[1]), "r"(a[2]), "r"(a[3]), "r"(b0), "r"(b1));
}
__device__ __forceinline__ float sigf(float x) {
    return 1.0f / (1.0f + __expf(-x));
}

// ---------------------------------------------------------------------------
// Fused weight pack (all 4 gates) via 32x32 smem transpose.
// dst selected DEVICE-SIDE (GB300 ATS silently accepts host shadow addresses
// of __device__ arrays passed as kernel args).
// ---------------------------------------------------------------------------
__global__ void prep_pack4(const float* __restrict__ s0, const float* __restrict__ s1,
                           const float* __restrict__ s2, const float* __restrict__ s3,
                           int Kdim, int is_wx)
{
    __shared__ __half tile[4][32][33];
    __half* __restrict__ dst = is_wx ? g_Wxp : g_Wp;
    const int k0 = blockIdx.x * 32;
    const int u0 = blockIdx.y * 32;
    const int tid = threadIdx.x;
    const int cx = tid & 31;
    const int ry = tid >> 5;
    const float* srcs[4] = { s0, s1, s2, s3 };

#pragma unroll
    for (int j = 0; j < 4; j++)
#pragma unroll
        for (int r = 0; r < 4; r++) {
            int ky = ry + r * 8;
            tile[j][ky][cx] = __float2half(srcs[j][(size_t)(k0 + ky) * HH + u0 + cx]);
        }
    __syncthreads();

#pragma unroll
    for (int j = 0; j < 4; j++)
#pragma unroll
        for (int r = 0; r < 4; r++) {
            int uy = ry + r * 8;
            int u = u0 + uy;
            int n = (u >> 3) * 32 + j * 8 + (u & 7);
            dst[(size_t)n * Kdim + k0 + cx] = tile[j][cx][uy];
        }
}

// Bias pack + h0 zero + barrier reset.
__global__ void prep_misc(const float* __restrict__ bf, const float* __restrict__ bi,
                          const float* __restrict__ bg, const float* __restrict__ bo)
{
    int idx = blockIdx.x * blockDim.x + threadIdx.x;
    if (idx < HH) {
        int u = idx;
        float bv[4] = { bf[u], bi[u], bg[u], bo[u] };
#pragma unroll
        for (int j = 0; j < 4; j++)
            g_bbp[(u >> 3) * 32 + j * 8 + (u & 7)] = bv[j];
    }
    if (idx < BB * HH)
        g_h[0][idx] = __float2half(0.0f);
    if (idx < 2) g_barc[idx] = 0;
}

// x fp32 -> g_xA fp16, rows r = t*128 + b
__global__ void prep_x(const float* __restrict__ x)
{
    int idx = blockIdx.x * blockDim.x + threadIdx.x;
    int i4 = idx * 4;
    int r = i4 >> 8;
    int d = i4 & (DD - 1);
    int b = r & (BB - 1);
    int t = r >> 7;
    float4 v = *(const float4*)(x + ((size_t)b * TT + t) * DD + d);
    __half2 p0 = __floats2half2_rn(v.x, v.y);
    __half2 p1 = __floats2half2_rn(v.z, v.w);
    uint2 o = { *(uint32_t*)&p0, *(uint32_t*)&p1 };
    *(uint2*)(g_xA + (size_t)r * DD + d) = o;
}

// ---------------------------------------------------------------------------
// Load one 128-row x 64-col fp16 chunk (xg_mma tiles, 256 thr), swizzled.
// ---------------------------------------------------------------------------
__device__ __forceinline__ void load_tile128(uint32_t dst,
                                             const __half* __restrict__ src,
                                             int kb, int row_stride, int tid)
{
    const int s  = tid & 7;
    const int r0 = tid >> 3;
    const int ke = kb + s * 8;
#pragma unroll
    for (int p = 0; p < 4; p++) {
        int row = r0 + p * 32;
        uint32_t off = row * 128 + s * 16;
        uint32_t sw  = off ^ ((off >> 3) & 0x70);
        cp_async16(dst + sw, src + (size_t)row * row_stride + ke);
    }
}

// Load one 64-row x 64-col fp16 subtile (recurrence A, 512 thr: 1 cp each).
__device__ __forceinline__ void load_tile64_512(uint32_t dst,
                                                const __half* __restrict__ src,
                                                int kb, int tid)
{
    const int s  = tid & 7;
    const int r  = tid >> 3;           // 0..63
    uint32_t off = r * 128 + s * 16;
    uint32_t sw  = off ^ ((off >> 3) & 0x70);
    cp_async16(dst + sw, src + (size_t)r * HH + kb + s * 8);
}

// Load one 128-K chunk (2 subtiles) into a 16KB buffer (512 thr).
__device__ __forceinline__ void load_chunk128_512(uint32_t buf,
                                                  const __half* __restrict__ src,
                                                  int kb, int tid)
{
    load_tile64_512(buf, src, kb, tid);
    load_tile64_512(buf + 8192, src, kb + 64, tid);
}

// ---------------------------------------------------------------------------
// xg = xA @ Wxp^T + bias (proven kernel, unchanged; 256 threads)
// ---------------------------------------------------------------------------
__global__ void __launch_bounds__(256) xg_mma()
{
    extern __shared__ __align__(1024) char smem[];
    const uint32_t sb = smem_u32(smem);
    const int tid = threadIdx.x;
    const int w = tid >> 5;
    const int lane = tid & 31;
    const int N0 = blockIdx.x * 128;
    const int m0 = blockIdx.y * 128;

    const __half* Asrc = g_xA + (size_t)m0 * DD;
    const __half* Bsrc = g_Wxp + (size_t)N0 * DD;

    load_tile128(sb + 0, Asrc, 0, DD, tid);
    load_tile128(sb + 16384, Bsrc, 0, DD, tid);
    CP_COMMIT();

    const uint32_t a_row_off = (uint32_t)(w * 16 + (lane & 15)) * 128 + (lane >> 4) * 16;

    float acc[16][4];
#pragma unroll
    for (int i = 0; i < 16; i++)
#pragma unroll
        for (int q = 0; q < 4; q++) acc[i][q] = 0.0f;

    for (int ch = 0; ch < 4; ch++) {
        if (ch + 1 < 4) {
            uint32_t nb = sb + ((ch + 1) & 1) * 32768;
            load_tile128(nb, Asrc, (ch + 1) * 64, DD, tid);
            load_tile128(nb + 16384, Bsrc, (ch + 1) * 64, DD, tid);
            CP_COMMIT();
            CP_WAIT(1);
        } else {
            CP_WAIT(0);
        }
        __syncthreads();

        const uint32_t ab = sb + (ch & 1) * 32768;
        const uint32_t bb = ab + 16384;

#pragma unroll
        for (int k16 = 0; k16 < 4; k16++) {
            uint32_t a[4];
            {
                uint32_t off = a_row_off + (uint32_t)(k16 * 32);
                uint32_t sw = off ^ ((off >> 3) & 0x70);
                ldmx4(a, ab + sw);
            }
            uint32_t b0[4][4], b1[4][4];
#pragma unroll
            for (int g = 0; g < 4; g++) {
                uint32_t off0 = (uint32_t)(g * 32 + lane) * 128 + (uint32_t)(k16 * 32);
                uint32_t sw0 = off0 ^ ((off0 >> 3) & 0x70);
                ldmx4(b0[g], bb + sw0);
                uint32_t off1 = off0 + 16;
                uint32_t sw1 = off1 ^ ((off1 >> 3) & 0x70);
                ldmx4(b1[g], bb + sw1);
            }
#pragma unroll
            for (int g = 0; g < 4; g++)
#pragma unroll
                for (int m = 0; m < 4; m++)
                    mma16816(acc[g * 4 + m], a, b0[g][m], b1[g][m]);
        }
        __syncthreads();
    }

    __half* cs = (__half*)smem;
    const int r0 = w * 16 + (lane >> 2);
    const int e2 = (lane & 3) * 2;
#pragma unroll
    for (int g = 0; g < 4; g++) {
#pragma unroll
        for (int j = 0; j < 4; j++) {
            const int bidx = g * 4 + j;
            float2 bias = *(const float2*)(g_bbp + N0 + g * 32 + j * 8 + e2);
            const int cl0 = (g * 8 + e2) * 4 + j;
            const int cl1 = cl0 + 4;
            cs[r0 * XCROWH + cl0]       = __float2half(acc[bidx][0] + bias.x);
            cs[r0 * XCROWH + cl1]       = __float2half(acc[bidx][1] + bias.y);
            cs[(r0 + 8) * XCROWH + cl0] = __float2half(acc[bidx][2] + bias.x);
            cs[(r0 + 8) * XCROWH + cl1] = __float2half(acc[bidx][3] + bias.y);
        }
    }
    __syncthreads();

    for (int i = tid; i < 128 * 16; i += 256) {
        int row = i >> 4, seg = i & 15;
        uint4 v = *(uint4*)(cs + row * XCROWH + seg * 8);
        *(uint4*)(g_xg + (size_t)(m0 + row) * N4 + N0 + seg * 8) = v;
    }
}

// ---------------------------------------------------------------------------
// Persistent LSTM recurrence, 512 threads = 16 warps: 2 k-groups x (4m x 2n).
// kg0 computes K 0..511 (chunks 0..3, bufs 0..2), kg1 computes K 512..1023
// (chunks 4..7, bufs 3..5) CONCURRENTLY. 4 supersteps/step, each computing
// one chunk per k-group. Load groups: G1(c0,c4) G2(c1,c5) prologue, G(p+2)
// issued inside superstep p (p<2) into bufs (p+2)%3 / 3+(p+2)%3 (drained by
// the sync). After the loop kg1 stages fp32 partials in smem (buf1 region),
// kg0 reduces + runs the proven fused epilogue. Barrier as in R15.
// ---------------------------------------------------------------------------
__global__ void __launch_bounds__(STEP_THR, 1) lstm_persist()
{
    extern __shared__ __align__(1024) char smem[];
    const uint32_t sb = smem_u32(smem);
    const int tid = threadIdx.x;
    const int w = tid >> 5;
    const int lane = tid & 31;
    const int mg = blockIdx.x >> 6;
    const int ng = blockIdx.x & 63;
    const int m_base = mg * 64;
    const int n0 = ng * 64;
    const int mw = w & 3;              // 0..3
    const int nw = (w >> 2) & 1;       // 0..1
    const int kg = w >> 3;             // 0..1

    // ---- one-time W tile load (64 x 1024 fp16); drains with first CP_WAIT ----
    {
        const __half* Wsrc = g_Wp + (size_t)n0 * HH;
        for (int i = tid; i < 8192; i += STEP_THR) {
            int n = i >> 7, s = i & 127;
            cp_async16(sb + S_WT + n * WROW + s * 16, Wsrc + (size_t)n * HH + s * 8);
        }
        CP_COMMIT();
    }

    const uint32_t wfrag = sb + S_WT + (uint32_t)(nw * 32 + lane) * WROW;
    const uint32_t a_row_off = (uint32_t)(mw * 16 + (lane & 15)) * 128 + (lane >> 4) * 16;

    const int row0 = m_base + mw * 16 + (lane >> 2);
    const int u0 = ng * 16 + nw * 8 + (lane & 3) * 2;
    const __half* xg_base0 = g_xg + (size_t)row0 * N4 + u0 * 4;
    const __half* xg_base1 = g_xg + (size_t)(row0 + 8) * N4 + u0 * 4;

    float creg[4] = { 0.0f, 0.0f, 0.0f, 0.0f };

    uint4 xq[2];
    if (kg == 0) {
        xq[0] = *(const uint4*)(xg_base0);
        xq[1] = *(const uint4*)(xg_base1);
    }

    float* const red = (float*)(smem + S_RED);
    unsigned* const barp = &g_barc[mg];

    for (int t = 0; t < TT; t++) {
        const int par = t & 1;
        const __half* A = g_h[par] + (size_t)m_base * HH;

        // prologue: G1(c0,c4) -> bufs 0,3 ; G2(c1,c5) -> bufs 1,4
        load_chunk128_512(sb + S_ABUF + 0 * ACH_SZ, A, 0, tid);
        load_chunk128_512(sb + S_ABUF + 3 * ACH_SZ, A, 512, tid);
        CP_COMMIT();
        load_chunk128_512(sb + S_ABUF + 1 * ACH_SZ, A, 128, tid);
        load_chunk128_512(sb + S_ABUF + 4 * ACH_SZ, A, 640, tid);
        CP_COMMIT();

        float acc[4][4];
#pragma unroll
        for (int j = 0; j < 4; j++)
#pragma unroll
            for (int q = 0; q < 4; q++) acc[j][q] = 0.0f;

#pragma unroll
        for (int p = 0; p < 4; p++) {
            if (p < 3) { CP_WAIT(1); } else { CP_WAIT(0); }
            __syncthreads();

            if (p + 2 < 4) {
                const int bi = (p + 2) % 3;
                load_chunk128_512(sb + S_ABUF + bi * ACH_SZ, A, (p + 2) * 128, tid);
                load_chunk128_512(sb + S_ABUF + (3 + bi) * ACH_SZ, A, 512 + (p + 2) * 128, tid);
                CP_COMMIT();
            }

            const int ch = kg * 4 + p;
            const uint32_t bufb = sb + S_ABUF + (uint32_t)(kg * 3 + (p % 3)) * ACH_SZ;
#pragma unroll
            for (int sub = 0; sub < 2; sub++) {
                const uint32_t stb = bufb + sub * 8192;
#pragma unroll
                for (int k16 = 0; k16 < 4; k16++) {
                    uint32_t ah[4];
                    uint32_t off = a_row_off + (uint32_t)(k16 * 32);
                    uint32_t sw = off ^ ((off >> 3) & 0x70);
                    ldmx4(ah, stb + sw);

                    const uint32_t kb = (uint32_t)(ch * 128 + sub * 64 + k16 * 16) * 2;
                    uint32_t b0[4], b1[4];
                    ldmx4(b0, wfrag + kb);
                    ldmx4(b1, wfrag + kb + 16);

#pragma unroll
                    for (int j = 0; j < 4; j++) mma16816(acc[j], ah, b0[j], b1[j]);
                }
            }
        }

        // ---- K-split reduction: kg1 stages partials, kg0 reduces ----
        if (kg == 1) {
            float* st = red + (size_t)((w - 8) * 32 + lane) * 16;
#pragma unroll
            for (int j = 0; j < 4; j++)
                *(float4*)(st + j * 4) = *(const float4*)acc[j];
        }
        __syncthreads();

        if (kg == 0) {
            const float* st = red + (size_t)(w * 32 + lane) * 16;
#pragma unroll
            for (int j = 0; j < 4; j++) {
                float4 pv = *(const float4*)(st + j * 4);
                acc[j][0] += pv.x; acc[j][1] += pv.y;
                acc[j][2] += pv.z; acc[j][3] += pv.w;
            }

            // ---- epilogue: fused gates, c in regs, write h fp16 ----
            __half* hout = g_h[par ^ 1];
#pragma unroll
            for (int rr = 0; rr < 2; rr++) {
                float2 fi0 = __half22float2(*(__half2*)&xq[rr].x);
                float2 go0 = __half22float2(*(__half2*)&xq[rr].y);
                float2 fi1 = __half22float2(*(__half2*)&xq[rr].z);
                float2 go1 = __half22float2(*(__half2*)&xq[rr].w);

                float hv[2];
                {
                    const int q = rr * 2;
                    float fg = sigf(acc[0][q] + fi0.x);
                    float ig = sigf(acc[1][q] + fi0.y);
                    float gg = tanhf(acc[2][q] + go0.x);
                    float og = sigf(acc[3][q] + go0.y);
                    float cn = gg * ig + creg[q] * fg;
                    creg[q] = cn;
                    hv[0] = tanhf(cn) * og;
                }
                {
                    const int q = rr * 2 + 1;
                    float fg = sigf(acc[0][q] + fi1.x);
                    float ig = sigf(acc[1][q] + fi1.y);
                    float gg = tanhf(acc[2][q] + go1.x);
                    float og = sigf(acc[3][q] + go1.y);
                    float cn = gg * ig + creg[q] * fg;
                    creg[q] = cn;
                    hv[1] = tanhf(cn) * og;
                }
                const int row = row0 + rr * 8;
                *(__half2*)(hout + (size_t)row * HH + u0) = __floats2half2_rn(hv[0], hv[1]);
            }

            // prefetch next step's xq (independent of h)
            if (t + 1 < TT) {
                const size_t toff = (size_t)(t + 1) * BB * N4;
                xq[0] = *(const uint4*)(xg_base0 + toff);
                xq[1] = *(const uint4*)(xg_base1 + toff);
            }
        }

        // ---- per-group grid barrier (64 CTAs; release-arrive by tid0) ----
        if (t < TT - 1) {
            __syncthreads();          // all h-writes of this CTA done
            if (tid == 0) {
                asm volatile("red.release.gpu.global.add.u32 [%0], 1;"
                             :: "l"(barp) : "memory");
                const unsigned target = 64u * (unsigned)(t + 1);
                unsigned v;
                do {
                    asm volatile("ld.global.acquire.gpu.b32 %0, [%1];"
                                 : "=r"(v) : "l"(barp));
                } while (v < target);
            }
            __syncthreads();
        }
    }
}

// ---------------------------------------------------------------------------
// Final projection
// ---------------------------------------------------------------------------
__global__ void proj_kernel(const float* __restrict__ Wph,
                            const float* __restrict__ bp,
                            float* __restrict__ out)
{
    const int b = blockIdx.x;
    const int w = threadIdx.x >> 5;
    const int lane = threadIdx.x & 31;
    const __half* hr = g_h[0] + (size_t)b * HH;

    float s = 0.0f;
    for (int h = lane; h < HH; h += 32)
        s += __half2float(hr[h]) * Wph[(size_t)h * CC + w];
#pragma unroll
    for (int off = 16; off; off >>= 1)
        s += __shfl_xor_sync(0xffffffffu, s, off);
    if (lane == 0)
        out[b * CC + w] = s + bp[w];
}

// ---------------------------------------------------------------------------
// Launch
// ---------------------------------------------------------------------------
extern "C" void kernel_launch(void* const* d_in, const int* in_sizes, int n_in,
                              void* d_out, int out_size)
{
    const float* x   = (const float*)d_in[0];
    const float* Wfx = (const float*)d_in[1];
    const float* Wix = (const float*)d_in[2];
    const float* Wgx = (const float*)d_in[3];
    const float* Wox = (const float*)d_in[4];
    const float* Wfh = (const float*)d_in[5];
    const float* Wih = (const float*)d_in[6];
    const float* Wgh = (const float*)d_in[7];
    const float* Woh = (const float*)d_in[8];
    const float* bf  = (const float*)d_in[9];
    const float* bi  = (const float*)d_in[10];
    const float* bg  = (const float*)d_in[11];
    const float* bo  = (const float*)d_in[12];
    const float* Wph = (const float*)d_in[13];
    const float* bp  = (const float*)d_in[14];
    float* out = (float*)d_out;

    cudaFuncSetAttribute(lstm_persist, cudaFuncAttributeMaxDynamicSharedMemorySize,
                         STEP_SMEM);
    cudaFuncSetAttribute(xg_mma, cudaFuncAttributeMaxDynamicSharedMemorySize,
                         XG_SMEM);

    // 1) fused weight pack + bias/h0/barriers
    prep_pack4<<<dim3(HH / 32, HH / 32), 256>>>(Wfh, Wih, Wgh, Woh, HH, 0);
    prep_pack4<<<dim3(DD / 32, HH / 32), 256>>>(Wfx, Wix, Wgx, Wox, DD, 1);
    prep_misc<<<(BB * HH + 255) / 256, 256>>>(bf, bi, bg, bo);

    // 2) x -> fp16
    prep_x<<<(TT * BB * DD / 4 + 255) / 256, 256>>>(x);

    // 3) input projections (fp16 MMA)
    xg_mma<<<dim3(N4 / 128, (TT * BB) / 128), 256, XG_SMEM>>>();

    // 4) persistent recurrence (16 warps, K-split, concurrent k-groups)
    lstm_persist<<<NCTA, STEP_THR, STEP_SMEM>>>();

    // 5) final projection
    proj_kernel<<<BB, CC * 32>>>(Wph, bp, out);
}

// round 17
// speedup vs baseline: 1.1141x; 1.1141x over previous
#include <cuda_runtime.h>
#include <cuda_fp16.h>
#include <math.h>
#include <stdint.h>

// Problem constants
#define BB 128      // batch
#define TT 256      // seq len
#define DD 256      // input dim
#define HH 1024     // hidden dim
#define CC 10       // classes
#define N4 4096     // 4*HH
#define NCTA 128    // persistent CTAs (one per SM)

// Step kernel constants
#define NTHR 256
#define WROW 2064                       // Wh row: 1024 fp16 = 2048B + 16B pad
#define WXROW 528                       // Wx row: 256 fp16 = 512B + 16B pad
#define S_WT 0                          // Wh tile: 64 x WROW = 132096
#define S_WX (64 * WROW)                // Wx tile: 64 x WXROW = 33792
#define S_ABUF (S_WX + 64 * WXROW)      // 165888
#define ACH_SZ 16384                    // one A chunk: 64 rows x 128 fp16 (2 subtiles)
#define STEP_SMEM (S_ABUF + 4 * ACH_SZ) // 231424 (<= 227KB opt-in)
#define NCH 10                          // chunks/step: 0-1 = x (K 256), 2-9 = h (K 1024)

// ---------------------------------------------------------------------------
// Device globals
// ---------------------------------------------------------------------------
__device__ __half g_xA[(size_t)TT * BB * DD];     // x rows r=t*128+b fp16
__device__ __half g_Wxp[(size_t)N4 * DD];         // Wx^T packed fp16
__device__ float  g_bbp[N4];                      // bias packed fp32
__device__ __half g_Wp[(size_t)N4 * HH];          // Wh^T packed fp16
__device__ __half g_h[2][BB * HH];                // h state fp16
__device__ unsigned g_barc[2];                    // per-mg-group grid barriers

// ---------------------------------------------------------------------------
// PTX helpers
// ---------------------------------------------------------------------------
__device__ __forceinline__ uint32_t smem_u32(const void* p) {
    uint32_t a;
    asm("{ .reg .u64 t; cvta.to.shared.u64 t, %1; cvt.u32.u64 %0, t; }" : "=r"(a) : "l"(p));
    return a;
}
__device__ __forceinline__ void cp_async16(uint32_t dst, const void* src) {
    asm volatile("cp.async.cg.shared.global [%0], [%1], 16;" :: "r"(dst), "l"(src));
}
#define CP_COMMIT() asm volatile("cp.async.commit_group;" ::: "memory")
#define CP_WAIT(n)  asm volatile("cp.async.wait_group %0;" :: "n"(n) : "memory")

__device__ __forceinline__ void ldmx4(uint32_t* r, uint32_t addr) {
    asm volatile("ldmatrix.sync.aligned.m8n8.x4.shared.b16 {%0,%1,%2,%3}, [%4];"
                 : "=r"(r[0]), "=r"(r[1]), "=r"(r[2]), "=r"(r[3]) : "r"(addr));
}
__device__ __forceinline__ void mma16816(float* d, const uint32_t* a, uint32_t b0, uint32_t b1) {
    asm volatile("mma.sync.aligned.m16n8k16.row.col.f32.f16.f16.f32 "
                 "{%0,%1,%2,%3}, {%4,%5,%6,%7}, {%8,%9}, {%0,%1,%2,%3};"
                 : "+f"(d[0]), "+f"(d[1]), "+f"(d[2]), "+f"(d[3])
                 : "r"(a[0]), "r"(a[1]), "r"(a[2]), "r"(a[3]), "r"(b0), "r"(b1));
}
__device__ __forceinline__ float sigf(float x) {
    return 1.0f / (1.0f + __expf(-x));
}

// ---------------------------------------------------------------------------
// Fused weight pack (all 4 gates) via 32x32 smem transpose.
// dst selected DEVICE-SIDE (GB300 ATS silently accepts host shadow addresses).
// ---------------------------------------------------------------------------
__global__ void prep_pack4(const float* __restrict__ s0, const float* __restrict__ s1,
                           const float* __restrict__ s2, const float* __restrict__ s3,
                           int Kdim, int is_wx)
{
    __shared__ __half tile[4][32][33];
    __half* __restrict__ dst = is_wx ? g_Wxp : g_Wp;
    const int k0 = blockIdx.x * 32;
    const int u0 = blockIdx.y * 32;
    const int tid = threadIdx.x;
    const int cx = tid & 31;
    const int ry = tid >> 5;
    const float* srcs[4] = { s0, s1, s2, s3 };

#pragma unroll
    for (int j = 0; j < 4; j++)
#pragma unroll
        for (int r = 0; r < 4; r++) {
            int ky = ry + r * 8;
            tile[j][ky][cx] = __float2half(srcs[j][(size_t)(k0 + ky) * HH + u0 + cx]);
        }
    __syncthreads();

#pragma unroll
    for (int j = 0; j < 4; j++)
#pragma unroll
        for (int r = 0; r < 4; r++) {
            int uy = ry + r * 8;
            int u = u0 + uy;
            int n = (u >> 3) * 32 + j * 8 + (u & 7);
            dst[(size_t)n * Kdim + k0 + cx] = tile[j][cx][uy];
        }
}

// Bias pack + h0 zero + barrier reset.
__global__ void prep_misc(const float* __restrict__ bf, const float* __restrict__ bi,
                          const float* __restrict__ bg, const float* __restrict__ bo)
{
    int idx = blockIdx.x * blockDim.x + threadIdx.x;
    if (idx < HH) {
        int u = idx;
        float bv[4] = { bf[u], bi[u], bg[u], bo[u] };
#pragma unroll
        for (int j = 0; j < 4; j++)
            g_bbp[(u >> 3) * 32 + j * 8 + (u & 7)] = bv[j];
    }
    if (idx < BB * HH)
        g_h[0][idx] = __float2half(0.0f);
    if (idx < 2) g_barc[idx] = 0;
}

// x fp32 -> g_xA fp16, rows r = t*128 + b
__global__ void prep_x(const float* __restrict__ x)
{
    int idx = blockIdx.x * blockDim.x + threadIdx.x;
    int i4 = idx * 4;
    int r = i4 >> 8;
    int d = i4 & (DD - 1);
    int b = r & (BB - 1);
    int t = r >> 7;
    float4 v = *(const float4*)(x + ((size_t)b * TT + t) * DD + d);
    __half2 p0 = __floats2half2_rn(v.x, v.y);
    __half2 p1 = __floats2half2_rn(v.z, v.w);
    uint2 o = { *(uint32_t*)&p0, *(uint32_t*)&p1 };
    *(uint2*)(g_xA + (size_t)r * DD + d) = o;
}

// Load one 64-row x 64-col fp16 subtile, swizzled (256 thr, 2 cp each).
// row_stride in halfs (HH for h, DD for x).
__device__ __forceinline__ void load_tile64(uint32_t dst,
                                            const __half* __restrict__ src,
                                            int kb, int row_stride, int tid)
{
    const int s  = tid & 7;
    const int row = tid >> 3;
#pragma unroll
    for (int p = 0; p < 2; p++) {
        int r = row + p * 32;
        uint32_t off = r * 128 + s * 16;
        uint32_t sw  = off ^ ((off >> 3) & 0x70);
        cp_async16(dst + sw, src + (size_t)r * row_stride + kb + s * 8);
    }
}

// ---------------------------------------------------------------------------
// Persistent LSTM recurrence with FUSED x-projection. R15-proven pipeline,
// extended to 10 chunks: 0-1 = x_t @ Wx^T (K 256), 2-9 = h_t @ Wh^T (K 1024).
// Wh (132KB) + Wx (34KB) resident in SMEM all 256 steps. Bias in registers.
// Next step's x chunks are issued BEFORE the barrier (h-independent), so
// their transfer hides under the barrier spin.
// ---------------------------------------------------------------------------
__global__ void __launch_bounds__(NTHR, 1) lstm_persist()
{
    extern __shared__ __align__(1024) char smem[];
    const uint32_t sb = smem_u32(smem);
    const int tid = threadIdx.x;
    const int w = tid >> 5;
    const int lane = tid & 31;
    const int mg = blockIdx.x >> 6;
    const int ng = blockIdx.x & 63;
    const int m_base = mg * 64;
    const int n0 = ng * 64;
    const int mw = w & 3;
    const int nw = w >> 2;

    // ---- one-time W tile loads (Wh 64x1024, Wx 64x256 fp16); 1 group ----
    {
        const __half* Wsrc = g_Wp + (size_t)n0 * HH;
        for (int i = tid; i < 8192; i += NTHR) {
            int n = i >> 7, s = i & 127;
            cp_async16(sb + S_WT + n * WROW + s * 16, Wsrc + (size_t)n * HH + s * 8);
        }
        const __half* Wxsrc = g_Wxp + (size_t)n0 * DD;
        for (int i = tid; i < 2048; i += NTHR) {
            int n = i >> 5, s = i & 31;
            cp_async16(sb + S_WX + n * WXROW + s * 16, Wxsrc + (size_t)n * DD + s * 8);
        }
        CP_COMMIT();
    }

    const uint32_t wfrag  = sb + S_WT + (uint32_t)(nw * 32 + lane) * WROW;
    const uint32_t wfragx = sb + S_WX + (uint32_t)(nw * 32 + lane) * WXROW;
    const uint32_t a_row_off = (uint32_t)(mw * 16 + (lane & 15)) * 128 + (lane >> 4) * 16;

    const int row0 = m_base + mw * 16 + (lane >> 2);
    const int u0 = ng * 16 + nw * 8 + (lane & 3) * 2;

    // bias registers: gate j, unit u0+uu  ->  g_bbp[(u0>>3)*32 + j*8 + (u0&7) + uu]
    float breg[4][2];
    {
        const int bb = (u0 >> 3) * 32 + (u0 & 7);
#pragma unroll
        for (int j = 0; j < 4; j++) {
            breg[j][0] = g_bbp[bb + j * 8 + 0];
            breg[j][1] = g_bbp[bb + j * 8 + 1];
        }
    }

    float creg[4] = { 0.0f, 0.0f, 0.0f, 0.0f };
    unsigned* const barp = &g_barc[mg];

    // prologue for t=0: x chunks 0,1 (buffers 0,1)
    {
        const __half* X = g_xA + (size_t)m_base * DD;   // t=0 rows
        load_tile64(sb + S_ABUF + 0 * ACH_SZ,        X, 0,   DD, tid);
        load_tile64(sb + S_ABUF + 0 * ACH_SZ + 8192, X, 64,  DD, tid);
        CP_COMMIT();
        load_tile64(sb + S_ABUF + 1 * ACH_SZ,        X, 128, DD, tid);
        load_tile64(sb + S_ABUF + 1 * ACH_SZ + 8192, X, 192, DD, tid);
        CP_COMMIT();
    }

    for (int t = 0; t < TT; t++) {
        const int par = t & 1;
        const __half* A = g_h[par] + (size_t)m_base * HH;

        // post-barrier prologue: first h chunk (chunk 2 -> buffer 2)
        {
            uint32_t db = sb + S_ABUF + 2 * ACH_SZ;
            load_tile64(db,        A, 0,  HH, tid);
            load_tile64(db + 8192, A, 64, HH, tid);
            CP_COMMIT();
        }

        float acc[4][4];
#pragma unroll
        for (int j = 0; j < 4; j++)
#pragma unroll
            for (int q = 0; q < 4; q++) acc[j][q] = 0.0f;

        for (int ch = 0; ch < NCH; ch++) {
            if (ch <= 7)      { CP_WAIT(2); }
            else if (ch == 8) { CP_WAIT(1); }
            else              { CP_WAIT(0); }
            __syncthreads();

            if (ch + 3 < NCH) {     // chunks 3..9 are h-chunks (K (ch+1)*128)
                uint32_t db = sb + S_ABUF + ((ch + 3) & 3) * ACH_SZ;
                load_tile64(db,        A, (ch + 1) * 128,      HH, tid);
                load_tile64(db + 8192, A, (ch + 1) * 128 + 64, HH, tid);
                CP_COMMIT();
            }

            const uint32_t ab = sb + S_ABUF + (ch & 3) * ACH_SZ;
            const int is_x = (ch < 2);
            const uint32_t bfr = is_x ? wfragx : wfrag;
            const int kbase = is_x ? ch * 128 : (ch - 2) * 128;
#pragma unroll
            for (int sub = 0; sub < 2; sub++) {
                const uint32_t stb = ab + sub * 8192;
#pragma unroll
                for (int k16 = 0; k16 < 4; k16++) {
                    uint32_t ah[4];
                    uint32_t off = a_row_off + (uint32_t)(k16 * 32);
                    uint32_t sw = off ^ ((off >> 3) & 0x70);
                    ldmx4(ah, stb + sw);

                    const uint32_t kb = (uint32_t)(kbase + sub * 64 + k16 * 16) * 2;
                    uint32_t b0[4], b1[4];
                    ldmx4(b0, bfr + kb);
                    ldmx4(b1, bfr + kb + 16);

#pragma unroll
                    for (int j = 0; j < 4; j++) mma16816(acc[j], ah, b0[j], b1[j]);
                }
            }
        }
        __syncthreads();   // all warps done with all A buffers

        // issue next step's x chunks (h-independent) -> hide under barrier
        if (t + 1 < TT) {
            const __half* X = g_xA + ((size_t)(t + 1) * BB + m_base) * DD;
            load_tile64(sb + S_ABUF + 0 * ACH_SZ,        X, 0,   DD, tid);
            load_tile64(sb + S_ABUF + 0 * ACH_SZ + 8192, X, 64,  DD, tid);
            CP_COMMIT();
            load_tile64(sb + S_ABUF + 1 * ACH_SZ,        X, 128, DD, tid);
            load_tile64(sb + S_ABUF + 1 * ACH_SZ + 8192, X, 192, DD, tid);
            CP_COMMIT();
        }

        // ---- epilogue: fused gates (bias from regs), c in regs, write h ----
        __half* hout = g_h[par ^ 1];
#pragma unroll
        for (int rr = 0; rr < 2; rr++) {
            float hv[2];
#pragma unroll
            for (int uu = 0; uu < 2; uu++) {
                const int q = rr * 2 + uu;
                float fg = sigf(acc[0][q] + breg[0][uu]);
                float ig = sigf(acc[1][q] + breg[1][uu]);
                float gg = tanhf(acc[2][q] + breg[2][uu]);
                float og = sigf(acc[3][q] + breg[3][uu]);
                float cn = gg * ig + creg[q] * fg;
                creg[q] = cn;
                hv[uu] = tanhf(cn) * og;
            }
            const int row = row0 + rr * 8;
            *(__half2*)(hout + (size_t)row * HH + u0) = __floats2half2_rn(hv[0], hv[1]);
        }

        // ---- per-group grid barrier (64 CTAs; release-arrive by tid0) ----
        if (t < TT - 1) {
            __syncthreads();
            if (tid == 0) {
                asm volatile("red.release.gpu.global.add.u32 [%0], 1;"
                             :: "l"(barp) : "memory");
                const unsigned target = 64u * (unsigned)(t + 1);
                unsigned v;
                do {
                    asm volatile("ld.global.acquire.gpu.b32 %0, [%1];"
                                 : "=r"(v) : "l"(barp));
                } while (v < target);
            }
            __syncthreads();
        }
    }
}

// ---------------------------------------------------------------------------
// Final projection
// ---------------------------------------------------------------------------
__global__ void proj_kernel(const float* __restrict__ Wph,
                            const float* __restrict__ bp,
                            float* __restrict__ out)
{
    const int b = blockIdx.x;
    const int w = threadIdx.x >> 5;
    const int lane = threadIdx.x & 31;
    const __half* hr = g_h[0] + (size_t)b * HH;

    float s = 0.0f;
    for (int h = lane; h < HH; h += 32)
        s += __half2float(hr[h]) * Wph[(size_t)h * CC + w];
#pragma unroll
    for (int off = 16; off; off >>= 1)
        s += __shfl_xor_sync(0xffffffffu, s, off);
    if (lane == 0)
        out[b * CC + w] = s + bp[w];
}

// ---------------------------------------------------------------------------
// Launch
// ---------------------------------------------------------------------------
extern "C" void kernel_launch(void* const* d_in, const int* in_sizes, int n_in,
                              void* d_out, int out_size)
{
    const float* x   = (const float*)d_in[0];
    const float* Wfx = (const float*)d_in[1];
    const float* Wix = (const float*)d_in[2];
    const float* Wgx = (const float*)d_in[3];
    const float* Wox = (const float*)d_in[4];
    const float* Wfh = (const float*)d_in[5];
    const float* Wih = (const float*)d_in[6];
    const float* Wgh = (const float*)d_in[7];
    const float* Woh = (const float*)d_in[8];
    const float* bf  = (const float*)d_in[9];
    const float* bi  = (const float*)d_in[10];
    const float* bg  = (const float*)d_in[11];
    const float* bo  = (const float*)d_in[12];
    const float* Wph = (const float*)d_in[13];
    const float* bp  = (const float*)d_in[14];
    float* out = (float*)d_out;

    cudaFuncSetAttribute(lstm_persist, cudaFuncAttributeMaxDynamicSharedMemorySize,
                         STEP_SMEM);

    // 1) fused weight pack + bias/h0/barriers
    prep_pack4<<<dim3(HH / 32, HH / 32), 256>>>(Wfh, Wih, Wgh, Woh, HH, 0);
    prep_pack4<<<dim3(DD / 32, HH / 32), 256>>>(Wfx, Wix, Wgx, Wox, DD, 1);
    prep_misc<<<(BB * HH + 255) / 256, 256>>>(bf, bi, bg, bo);

    // 2) x -> fp16
    prep_x<<<(TT * BB * DD / 4 + 255) / 256, 256>>>(x);

    // 3) persistent recurrence with fused x-projection (NO xg kernel)
    lstm_persist<<<NCTA, NTHR, STEP_SMEM>>>();

    // 4) final projection
    proj_kernel<<<BB, CC * 32>>>(Wph, bp, out);
}